// round 15
// baseline (speedup 1.0000x reference)
#include <cuda_runtime.h>
#include <math.h>

#define B_DIM 4
#define T_DIM 96
#define N_DIM 512
#define ROW_LEN 514            // 2 + N
#define EPS 1e-8f
#define CTAS_PER_BATCH 64
#define NODES_PER_CTA 8
#define GRID_CTAS (B_DIM * CTAS_PER_BATCH)   // 256
#define BLOCK_THREADS 512                    // 8 scan warps + 8 producer warps
#define LEAD 12                              // producer lead cap (L2 window)

// Per-batch cumulative arrival counter. Value t*64 => step t-1 fully published.
__device__ unsigned int g_bar_arrive[B_DIM];
// Double-buffered packed I vectors: step t reads g_I[t&1], writes g_I[(t+1)&1].
__device__ float g_I[2][B_DIM][N_DIM];

// Re-initialize all cross-launch state each call (graph-replay determinism).
__global__ void init_kernel(const float* __restrict__ x0)
{
    const int idx = blockIdx.x * 256 + threadIdx.x;        // 0..2047
    if (idx < B_DIM * N_DIM) {
        const int b = idx >> 9, n = idx & 511;
        g_I[0][b][n] = x0[((long)b * N_DIM + n) * 3 + 1];  // I component
    }
    if (idx < B_DIM) g_bar_arrive[idx] = 0u;
}

__device__ __forceinline__ unsigned int ld_acquire_gpu(const unsigned int* p)
{
    unsigned int v;
    asm volatile("ld.acquire.gpu.global.u32 %0, [%1];" : "=r"(v) : "l"(p) : "memory");
    return v;
}

// ---------------------------------------------------------------------------
// Warp-specialized persistent kernel. 256 CTAs x 512 threads.
//   Warps 8..15 (producers): free-running softmax -> ep (LEAD-throttled).
//   Warps 0..7 (scan): per step: smem-flag wait -> c row loads -> PER-WARP
//     acquire-poll of the batch counter -> direct __ldcg of packed I (no smem
//     staging, no staging barriers) -> dot -> register SIR update -> g_I/ov
//     stores -> ONE bar.sync -> thread-0 fence+atomic publish.
// Co-residency: 256 CTAs @ __launch_bounds__(512,2) on 148 SMs => 296 slots,
// all wave-1 resident; spins cannot deadlock.
// ---------------------------------------------------------------------------
__global__ __launch_bounds__(BLOCK_THREADS, 2)
void ssir_ws_kernel(const float* __restrict__ x0,
                    const float* __restrict__ params,
                    float* __restrict__ ov,    // (B,T,N,3)
                    float* __restrict__ ep)    // (B,T,N,514)
{
    __shared__ volatile int prod_step[NODES_PER_CTA];  // producer progress
    __shared__ volatile int scan_prog[NODES_PER_CTA];  // scan progress (backpressure)

    const int b    = blockIdx.x >> 6;
    const int n0   = (blockIdx.x & 63) * NODES_PER_CTA;
    const int w    = threadIdx.x >> 5;
    const int lane = threadIdx.x & 31;

    if (threadIdx.x < NODES_PER_CTA) {
        prod_step[threadIdx.x] = 0;
        scan_prog[threadIdx.x] = 0;
    }
    __syncthreads();   // only block-wide sync; before warp specialization

    const long row_stride = (long)N_DIM * ROW_LEN;

    if (w >= 8) {
        // ================= PRODUCER =================
        const int p = w - 8;
        const int n = n0 + p;
        const float* in0  = params + (((long)b * T_DIM) * N_DIM + n) * ROW_LEN;
        float*       out0 = ep     + (((long)b * T_DIM) * N_DIM + n) * ROW_LEN;

        for (int t = 0; t < T_DIM; t++) {
            // backpressure: keep the ep window L2-resident for the scan
            while (t > scan_prog[p] + LEAD) { __nanosleep(64); }

            const float* in  = in0  + (long)t * row_stride;
            float*       out = out0 + (long)t * row_stride;

            const float2 bg = *reinterpret_cast<const float2*>(in);
            const float2* in2 = reinterpret_cast<const float2*>(in + 2);
            float2 v[8];
#pragma unroll
            for (int k = 0; k < 8; k++) v[k] = __ldcs(&in2[lane + 32 * k]);

            float m = -INFINITY;
#pragma unroll
            for (int k = 0; k < 8; k++) m = fmaxf(m, fmaxf(v[k].x, v[k].y));
#pragma unroll
            for (int o = 16; o > 0; o >>= 1) m = fmaxf(m, __shfl_xor_sync(0xFFFFFFFFu, m, o));

            float s = 0.f;
#pragma unroll
            for (int k = 0; k < 8; k++) {
                v[k].x = __expf(v[k].x - m);
                v[k].y = __expf(v[k].y - m);
                s += v[k].x + v[k].y;
            }
#pragma unroll
            for (int o = 16; o > 0; o >>= 1) s += __shfl_xor_sync(0xFFFFFFFFu, s, o);
            const float inv = 1.0f / s;

            float2* out2 = reinterpret_cast<float2*>(out + 2);
#pragma unroll
            for (int k = 0; k < 8; k++) {
                float2 wv; wv.x = v[k].x * inv; wv.y = v[k].y * inv;
                out2[lane + 32 * k] = wv;          // normal store: stay L2-hot
            }
            if (lane == 0) {
                float2 r;
                r.x = 1.0f / (1.0f + __expf(-bg.x));   // beta
                r.y = 1.0f / (1.0f + __expf(-bg.y));   // gamma
                *reinterpret_cast<float2*>(out) = r;   // ep row base 8B-aligned
            }

            __syncwarp();                               // all lanes' STGs issued
            if (lane == 0) {
                __threadfence_block();                  // release (intra-CTA)
                prod_step[p] = t + 1;
            }
        }
    } else {
        // ================= SCAN =================
        const int s = w;
        const int n = n0 + s;
        const unsigned int* bar = &g_bar_arrive[b];

        // State lives in lane-0 registers for the whole scan.
        float S = 0.f, In = 0.f, R = 0.f;
        if (lane == 0) {
            const float* xr = x0 + ((long)b * N_DIM + n) * 3;
            S = xr[0]; In = xr[1]; R = xr[2];
        }

        const float* crow0 = ep + (((long)b * T_DIM) * N_DIM + n) * ROW_LEN;

        for (int t = 0; t < T_DIM; t++) {
            // -- wait for this node's c row (producer smem flag), acquire
            while (prod_step[s] < t + 1) { }
            __threadfence_block();

            // -- issue c row loads (drain during the counter poll)
            const float* crow = crow0 + (long)t * row_stride;
            const float2* c2 = reinterpret_cast<const float2*>(crow + 2);
            float2 v[8];
#pragma unroll
            for (int k = 0; k < 8; k++) v[k] = c2[lane + 32 * k];
            float beta = 0.f, gamma = 0.f;
            if (lane == 0) {
                const float2 bgv = *reinterpret_cast<const float2*>(crow);
                beta = bgv.x; gamma = bgv.y;
            }

            // -- per-warp acquire-poll: step t-1's I fully published?
            {
                const unsigned int need = (unsigned int)t * CTAS_PER_BATCH;
                while (ld_acquire_gpu(bar) < need) { }
            }

            // -- direct coalesced I loads (L2, bypass L1 for freshness)
            const float2* Ib = reinterpret_cast<const float2*>(g_I[t & 1][b]);
            float2 iv[8];
#pragma unroll
            for (int k = 0; k < 8; k++) iv[k] = __ldcg(&Ib[lane + 32 * k]);

            // -- dot(c_row, I)
            float acc = 0.f;
#pragma unroll
            for (int k = 0; k < 8; k++) {
                acc = fmaf(v[k].x, iv[k].x, acc);
                acc = fmaf(v[k].y, iv[k].y, acc);
            }
#pragma unroll
            for (int o = 16; o > 0; o >>= 1) acc += __shfl_xor_sync(0xFFFFFFFFu, acc, o);

            if (lane == 0) {
                const float Npop = fmaxf(S + In + R, EPS);

                const float dS = -beta * S / Npop * acc;
                const float dR = gamma * In;
                const float dI = -dS - dR;

                float St = fmaxf(S + dS, 0.f);
                float It = fmaxf(In + dI, 0.f);
                float Rt = fmaxf(R + dR, 0.f);

                const float scale = Npop / fmaxf(St + It + Rt, EPS);
                St *= scale; It *= scale; Rt *= scale;

                float* o = ov + (((long)b * T_DIM + t) * N_DIM + n) * 3;
                o[0] = St; o[1] = It; o[2] = Rt;
                g_I[(t + 1) & 1][b][n] = It;   // packed I for step t+1

                S = St; In = It; R = Rt;

                scan_prog[s] = t + 1;          // release producer backpressure
            }

            // -- single per-step barrier: all 8 scan warps' g_I writes issued
            asm volatile("bar.sync 1, 256;" ::: "memory");
            if (threadIdx.x == 0) {
                __threadfence();               // release (cumulative)
                atomicAdd(&g_bar_arrive[b], 1u);
            }
        }
    }
}

// ---------------------------------------------------------------------------
extern "C" void kernel_launch(void* const* d_in, const int* in_sizes, int n_in,
                              void* d_out, int out_size)
{
    // Robust to metadata ordering: x0 has 6144 elems, params 101,056,512.
    const float* x0     = (const float*)d_in[0];
    const float* params = (const float*)d_in[1];
    if (in_sizes[0] > in_sizes[1]) {
        x0     = (const float*)d_in[1];
        params = (const float*)d_in[0];
    }
    float* outp = (float*)d_out;

    const long OV_SIZE = (long)B_DIM * T_DIM * N_DIM * 3;
    float* ov = outp;                 // output_view (B,T,N,3)
    float* ep = outp + OV_SIZE;       // epiparams   (B,T,N,514)

    init_kernel<<<8, 256>>>(x0);
    ssir_ws_kernel<<<GRID_CTAS, BLOCK_THREADS>>>(x0, params, ov, ep);
}

// round 16
// speedup vs baseline: 1.6763x; 1.6763x over previous
#include <cuda_runtime.h>
#include <math.h>

#define B_DIM 4
#define T_DIM 96
#define N_DIM 512
#define ROW_LEN 514            // 2 + N
#define EPS 1e-8f
#define CTAS_PER_BATCH 64
#define NODES_PER_CTA 8
#define GRID_CTAS (B_DIM * CTAS_PER_BATCH)   // 256
#define BLOCK_THREADS 512                    // 8 scan warps + 8 producer warps
#define LEAD 12                              // producer lead cap (L2 window)

// Per-batch cumulative arrival counter. Value t*64 => step t-1 fully published.
__device__ unsigned int g_bar_arrive[B_DIM];
// Double-buffered packed I vectors: step t reads g_I[t&1], writes g_I[(t+1)&1].
__device__ float g_I[2][B_DIM][N_DIM];

// Re-initialize all cross-launch state each call (graph-replay determinism).
__global__ void init_kernel(const float* __restrict__ x0)
{
    const int idx = blockIdx.x * 256 + threadIdx.x;        // 0..2047
    if (idx < B_DIM * N_DIM) {
        const int b = idx >> 9, n = idx & 511;
        g_I[0][b][n] = x0[((long)b * N_DIM + n) * 3 + 1];  // I component
    }
    if (idx < B_DIM) g_bar_arrive[idx] = 0u;
}

// ---------------------------------------------------------------------------
// Warp-specialized persistent kernel. 256 CTAs x 512 threads.
//   Warps 8..15 (producers): free-running softmax -> ep (LEAD-throttled),
//     no barrier participation.
//   Warps 0..7 (scan): per step: smem-flag wait -> c-row loads -> THREAD-0-
//     ONLY poll of the per-batch counter (64 pollers total, not 512 — per-
//     warp polling measured catastrophic in R15) -> fence -> bar.sync
//     broadcast -> per-warp direct __ldcg of packed I (no smem staging) ->
//     dot -> register SIR update -> ONE pre-publish bar.sync -> fence+atomic.
// Co-residency: 256 CTAs @ __launch_bounds__(512,2) on 148 SMs => 296 slots,
// all wave-1 resident; spins cannot deadlock.
// ---------------------------------------------------------------------------
__global__ __launch_bounds__(BLOCK_THREADS, 2)
void ssir_ws_kernel(const float* __restrict__ x0,
                    const float* __restrict__ params,
                    float* __restrict__ ov,    // (B,T,N,3)
                    float* __restrict__ ep)    // (B,T,N,514)
{
    __shared__ volatile int prod_step[NODES_PER_CTA];  // producer progress
    __shared__ volatile int scan_prog[NODES_PER_CTA];  // scan progress (backpressure)

    const int b    = blockIdx.x >> 6;
    const int n0   = (blockIdx.x & 63) * NODES_PER_CTA;
    const int w    = threadIdx.x >> 5;
    const int lane = threadIdx.x & 31;

    if (threadIdx.x < NODES_PER_CTA) {
        prod_step[threadIdx.x] = 0;
        scan_prog[threadIdx.x] = 0;
    }
    __syncthreads();   // only block-wide sync; before warp specialization

    const long row_stride = (long)N_DIM * ROW_LEN;

    if (w >= 8) {
        // ================= PRODUCER =================
        const int p = w - 8;
        const int n = n0 + p;
        const float* in0  = params + (((long)b * T_DIM) * N_DIM + n) * ROW_LEN;
        float*       out0 = ep     + (((long)b * T_DIM) * N_DIM + n) * ROW_LEN;

        for (int t = 0; t < T_DIM; t++) {
            // backpressure: keep the ep window L2-resident for the scan
            while (t > scan_prog[p] + LEAD) { __nanosleep(64); }

            const float* in  = in0  + (long)t * row_stride;
            float*       out = out0 + (long)t * row_stride;

            const float2 bg = *reinterpret_cast<const float2*>(in);
            const float2* in2 = reinterpret_cast<const float2*>(in + 2);
            float2 v[8];
#pragma unroll
            for (int k = 0; k < 8; k++) v[k] = __ldcs(&in2[lane + 32 * k]);

            float m = -INFINITY;
#pragma unroll
            for (int k = 0; k < 8; k++) m = fmaxf(m, fmaxf(v[k].x, v[k].y));
#pragma unroll
            for (int o = 16; o > 0; o >>= 1) m = fmaxf(m, __shfl_xor_sync(0xFFFFFFFFu, m, o));

            float s = 0.f;
#pragma unroll
            for (int k = 0; k < 8; k++) {
                v[k].x = __expf(v[k].x - m);
                v[k].y = __expf(v[k].y - m);
                s += v[k].x + v[k].y;
            }
#pragma unroll
            for (int o = 16; o > 0; o >>= 1) s += __shfl_xor_sync(0xFFFFFFFFu, s, o);
            const float inv = 1.0f / s;

            float2* out2 = reinterpret_cast<float2*>(out + 2);
#pragma unroll
            for (int k = 0; k < 8; k++) {
                float2 wv; wv.x = v[k].x * inv; wv.y = v[k].y * inv;
                out2[lane + 32 * k] = wv;          // normal store: stay L2-hot
            }
            if (lane == 0) {
                float2 r;
                r.x = 1.0f / (1.0f + __expf(-bg.x));   // beta
                r.y = 1.0f / (1.0f + __expf(-bg.y));   // gamma
                *reinterpret_cast<float2*>(out) = r;   // ep row base 8B-aligned
            }

            __syncwarp();                               // all lanes' STGs issued
            if (lane == 0) {
                __threadfence_block();                  // release (intra-CTA)
                prod_step[p] = t + 1;
            }
        }
    } else {
        // ================= SCAN =================
        const int s = w;
        const int n = n0 + s;
        volatile unsigned int* bar = &g_bar_arrive[b];

        // State lives in lane-0 registers for the whole scan.
        float S = 0.f, In = 0.f, R = 0.f;
        if (lane == 0) {
            const float* xr = x0 + ((long)b * N_DIM + n) * 3;
            S = xr[0]; In = xr[1]; R = xr[2];
        }

        const float* crow0 = ep + (((long)b * T_DIM) * N_DIM + n) * ROW_LEN;

        for (int t = 0; t < T_DIM; t++) {
            // -- wait for this node's c row (producer smem flag), acquire
            while (prod_step[s] < t + 1) { }
            __threadfence_block();

            // -- issue c row loads (drain during the counter poll)
            const float* crow = crow0 + (long)t * row_stride;
            const float2* c2 = reinterpret_cast<const float2*>(crow + 2);
            float2 v[8];
#pragma unroll
            for (int k = 0; k < 8; k++) v[k] = c2[lane + 32 * k];
            float beta = 0.f, gamma = 0.f;
            if (lane == 0) {
                const float2 bgv = *reinterpret_cast<const float2*>(crow);
                beta = bgv.x; gamma = bgv.y;
            }

            // -- thread-0-only poll: step t-1's I fully published?
            if (t > 0) {
                if (threadIdx.x == 0) {
                    const unsigned int need = (unsigned int)t * CTAS_PER_BATCH;
                    while (*bar < need) { }   // 64 pollers chip-wide, tight spin
                    __threadfence();          // acquire
                }
            }
            asm volatile("bar.sync 1, 256;" ::: "memory");   // broadcast

            // -- per-warp direct coalesced I loads (no smem staging)
            const float2* Ib = reinterpret_cast<const float2*>(g_I[t & 1][b]);
            float2 iv[8];
#pragma unroll
            for (int k = 0; k < 8; k++) iv[k] = __ldcg(&Ib[lane + 32 * k]);

            // -- dot(c_row, I)
            float acc = 0.f;
#pragma unroll
            for (int k = 0; k < 8; k++) {
                acc = fmaf(v[k].x, iv[k].x, acc);
                acc = fmaf(v[k].y, iv[k].y, acc);
            }
#pragma unroll
            for (int o = 16; o > 0; o >>= 1) acc += __shfl_xor_sync(0xFFFFFFFFu, acc, o);

            if (lane == 0) {
                const float Npop = fmaxf(S + In + R, EPS);

                const float dS = -beta * S / Npop * acc;
                const float dR = gamma * In;
                const float dI = -dS - dR;

                float St = fmaxf(S + dS, 0.f);
                float It = fmaxf(In + dI, 0.f);
                float Rt = fmaxf(R + dR, 0.f);

                const float scale = Npop / fmaxf(St + It + Rt, EPS);
                St *= scale; It *= scale; Rt *= scale;

                float* o = ov + (((long)b * T_DIM + t) * N_DIM + n) * 3;
                o[0] = St; o[1] = It; o[2] = Rt;
                g_I[(t + 1) & 1][b][n] = It;   // packed I for step t+1

                S = St; In = It; R = Rt;

                scan_prog[s] = t + 1;          // release producer backpressure
            }

            // -- pre-publish barrier: all 8 scan warps' g_I writes issued
            asm volatile("bar.sync 1, 256;" ::: "memory");
            if (threadIdx.x == 0) {
                __threadfence();               // release (cumulative)
                atomicAdd(&g_bar_arrive[b], 1u);
            }
        }
    }
}

// ---------------------------------------------------------------------------
extern "C" void kernel_launch(void* const* d_in, const int* in_sizes, int n_in,
                              void* d_out, int out_size)
{
    // Robust to metadata ordering: x0 has 6144 elems, params 101,056,512.
    const float* x0     = (const float*)d_in[0];
    const float* params = (const float*)d_in[1];
    if (in_sizes[0] > in_sizes[1]) {
        x0     = (const float*)d_in[1];
        params = (const float*)d_in[0];
    }
    float* outp = (float*)d_out;

    const long OV_SIZE = (long)B_DIM * T_DIM * N_DIM * 3;
    float* ov = outp;                 // output_view (B,T,N,3)
    float* ep = outp + OV_SIZE;       // epiparams   (B,T,N,514)

    init_kernel<<<8, 256>>>(x0);
    ssir_ws_kernel<<<GRID_CTAS, BLOCK_THREADS>>>(x0, params, ov, ep);
}

// round 17
// speedup vs baseline: 2.3092x; 1.3775x over previous
#include <cuda_runtime.h>
#include <math.h>

#define B_DIM 4
#define T_DIM 96
#define N_DIM 512
#define ROW_LEN 514            // 2 + N
#define EPS 1e-8f
#define CTAS_PER_BATCH 32
#define NODES_PER_CTA 16
#define GRID_CTAS (B_DIM * CTAS_PER_BATCH)   // 128
#define BLOCK_THREADS 1024                   // 16 scan warps + 16 producer warps
#define SCAN_THREADS 512
#define LEAD 12                              // producer lead cap (L2 window)

// Per-batch cumulative arrival counter. Value t*32 => step t-1 fully published.
__device__ unsigned int g_bar_arrive[B_DIM];
// Double-buffered packed I vectors: step t reads g_I[t&1], writes g_I[(t+1)&1].
__device__ float g_I[2][B_DIM][N_DIM];

__global__ void init_kernel(const float* __restrict__ x0)
{
    const int idx = blockIdx.x * 256 + threadIdx.x;        // 0..2047
    if (idx < B_DIM * N_DIM) {
        const int b = idx >> 9, n = idx & 511;
        g_I[0][b][n] = x0[((long)b * N_DIM + n) * 3 + 1];  // I component
    }
    if (idx < B_DIM) g_bar_arrive[idx] = 0u;
}

__device__ __forceinline__ unsigned int ld_acquire_gpu(const unsigned int* p)
{
    unsigned int v;
    asm volatile("ld.acquire.gpu.global.u32 %0, [%1];" : "=r"(v) : "l"(p) : "memory");
    return v;
}
__device__ __forceinline__ void red_release_gpu_add(unsigned int* p, unsigned int v)
{
    asm volatile("red.release.gpu.global.add.u32 [%0], %1;" :: "l"(p), "r"(v) : "memory");
}
__device__ __forceinline__ void st_release_cta(volatile int* p, int v)
{
    asm volatile("st.release.cta.s32 [%0], %1;" :: "l"((int*)p), "r"(v) : "memory");
}
__device__ __forceinline__ int ld_acquire_cta(volatile int* p)
{
    int v;
    asm volatile("ld.acquire.cta.s32 %0, [%1];" : "=r"(v) : "l"((int*)p) : "memory");
    return v;
}

// ---------------------------------------------------------------------------
// Warp-specialized persistent kernel. 128 CTAs x 1024 threads (32/batch).
//   Warps 16..31 (producers): free-running softmax -> ep, LEAD-throttled,
//     release handoff via st.release.cta smem flag (no membar).
//   Warps 0..15 (scan): per step: acquire smem flag -> c-row loads ->
//     thread-0-only ld.acquire.gpu poll (32 pollers/batch-counter chip-wide)
//     -> bar.sync broadcast -> smem-staged I (single coalesced read/CTA;
//     per-warp duplication measured catastrophic in R16) -> dot -> register
//     SIR update -> pre-publish bar.sync -> red.release.gpu (no membar).
// Co-residency: 128 CTAs @ __launch_bounds__(1024,1) on 148 SMs => wave-1.
// ---------------------------------------------------------------------------
__global__ __launch_bounds__(BLOCK_THREADS, 1)
void ssir_ws_kernel(const float* __restrict__ x0,
                    const float* __restrict__ params,
                    float* __restrict__ ov,    // (B,T,N,3)
                    float* __restrict__ ep)    // (B,T,N,514)
{
    __shared__ float sI[N_DIM];
    __shared__ volatile int prod_step[NODES_PER_CTA];  // producer progress
    __shared__ volatile int scan_prog[NODES_PER_CTA];  // scan progress (backpressure)

    const int b    = blockIdx.x >> 5;                   // 32 CTAs per batch
    const int n0   = (blockIdx.x & 31) * NODES_PER_CTA;
    const int w    = threadIdx.x >> 5;
    const int lane = threadIdx.x & 31;

    if (threadIdx.x < NODES_PER_CTA) {
        prod_step[threadIdx.x] = 0;
        scan_prog[threadIdx.x] = 0;
    }
    __syncthreads();   // only block-wide sync; before warp specialization

    const long row_stride = (long)N_DIM * ROW_LEN;

    if (w >= 16) {
        // ================= PRODUCER =================
        const int p = w - 16;
        const int n = n0 + p;
        const float* in0  = params + (((long)b * T_DIM) * N_DIM + n) * ROW_LEN;
        float*       out0 = ep     + (((long)b * T_DIM) * N_DIM + n) * ROW_LEN;

        for (int t = 0; t < T_DIM; t++) {
            // backpressure: keep the ep window L2-resident for the scan
            while (t > scan_prog[p] + LEAD) { __nanosleep(64); }

            const float* in  = in0  + (long)t * row_stride;
            float*       out = out0 + (long)t * row_stride;

            const float2 bg = *reinterpret_cast<const float2*>(in);
            const float2* in2 = reinterpret_cast<const float2*>(in + 2);
            float2 v[8];
#pragma unroll
            for (int k = 0; k < 8; k++) v[k] = __ldcs(&in2[lane + 32 * k]);

            float m = -INFINITY;
#pragma unroll
            for (int k = 0; k < 8; k++) m = fmaxf(m, fmaxf(v[k].x, v[k].y));
#pragma unroll
            for (int o = 16; o > 0; o >>= 1) m = fmaxf(m, __shfl_xor_sync(0xFFFFFFFFu, m, o));

            float s = 0.f;
#pragma unroll
            for (int k = 0; k < 8; k++) {
                v[k].x = __expf(v[k].x - m);
                v[k].y = __expf(v[k].y - m);
                s += v[k].x + v[k].y;
            }
#pragma unroll
            for (int o = 16; o > 0; o >>= 1) s += __shfl_xor_sync(0xFFFFFFFFu, s, o);
            const float inv = 1.0f / s;

            float2* out2 = reinterpret_cast<float2*>(out + 2);
#pragma unroll
            for (int k = 0; k < 8; k++) {
                float2 wv; wv.x = v[k].x * inv; wv.y = v[k].y * inv;
                out2[lane + 32 * k] = wv;          // normal store: stay L2-hot
            }
            if (lane == 0) {
                float2 r;
                r.x = 1.0f / (1.0f + __expf(-bg.x));   // beta
                r.y = 1.0f / (1.0f + __expf(-bg.y));   // gamma
                *reinterpret_cast<float2*>(out) = r;   // ep row base 8B-aligned
            }

            __syncwarp();                               // all lanes' STGs issued
            if (lane == 0) {
                st_release_cta(&prod_step[p], t + 1);   // release handoff
            }
        }
    } else {
        // ================= SCAN =================
        const int s = w;
        const int n = n0 + s;
        unsigned int* bar = &g_bar_arrive[b];

        // State lives in lane-0 registers for the whole scan.
        float S = 0.f, In = 0.f, R = 0.f;
        if (lane == 0) {
            const float* xr = x0 + ((long)b * N_DIM + n) * 3;
            S = xr[0]; In = xr[1]; R = xr[2];
        }

        const float* crow0 = ep + (((long)b * T_DIM) * N_DIM + n) * ROW_LEN;

        for (int t = 0; t < T_DIM; t++) {
            // -- wait for this node's c row (producer flag), acquire
            while (ld_acquire_cta(&prod_step[s]) < t + 1) { }

            // -- issue c row loads (drain during the counter poll)
            const float* crow = crow0 + (long)t * row_stride;
            const float2* c2 = reinterpret_cast<const float2*>(crow + 2);
            float2 v[8];
#pragma unroll
            for (int k = 0; k < 8; k++) v[k] = c2[lane + 32 * k];
            float beta = 0.f, gamma = 0.f;
            if (lane == 0) {
                const float2 bgv = *reinterpret_cast<const float2*>(crow);
                beta = bgv.x; gamma = bgv.y;
            }

            // -- thread-0-only acquire-poll: step t-1's I fully published?
            if (t > 0) {
                if (threadIdx.x == 0) {
                    const unsigned int need = (unsigned int)t * CTAS_PER_BATCH;
                    while (ld_acquire_gpu(bar) < need) { }
                }
            }
            asm volatile("bar.sync 1, 512;" ::: "memory");   // broadcast

            // -- stage packed I ONCE per CTA (threads 0..127, float4s)
            if (threadIdx.x < N_DIM / 4) {
                const float4* p4 = reinterpret_cast<const float4*>(g_I[t & 1][b]);
                reinterpret_cast<float4*>(sI)[threadIdx.x] = p4[threadIdx.x];
            }
            asm volatile("bar.sync 1, 512;" ::: "memory");

            // -- dot(c_row, I)
            float acc = 0.f;
#pragma unroll
            for (int k = 0; k < 8; k++) {
                const int j = lane + 32 * k;
                acc = fmaf(v[k].x, sI[2 * j],     acc);
                acc = fmaf(v[k].y, sI[2 * j + 1], acc);
            }
#pragma unroll
            for (int o = 16; o > 0; o >>= 1) acc += __shfl_xor_sync(0xFFFFFFFFu, acc, o);

            if (lane == 0) {
                const float Npop = fmaxf(S + In + R, EPS);

                const float dS = -beta * S / Npop * acc;
                const float dR = gamma * In;
                const float dI = -dS - dR;

                float St = fmaxf(S + dS, 0.f);
                float It = fmaxf(In + dI, 0.f);
                float Rt = fmaxf(R + dR, 0.f);

                const float scale = Npop / fmaxf(St + It + Rt, EPS);
                St *= scale; It *= scale; Rt *= scale;

                float* o = ov + (((long)b * T_DIM + t) * N_DIM + n) * 3;
                o[0] = St; o[1] = It; o[2] = Rt;
                g_I[(t + 1) & 1][b][n] = It;   // packed I for step t+1

                S = St; In = It; R = Rt;

                scan_prog[s] = t + 1;          // release producer backpressure
            }

            // -- pre-publish barrier: all 16 scan warps' g_I writes issued
            asm volatile("bar.sync 1, 512;" ::: "memory");
            if (threadIdx.x == 0) {
                red_release_gpu_add(bar, 1u);  // fence-free publish
            }
        }
    }
}

// ---------------------------------------------------------------------------
extern "C" void kernel_launch(void* const* d_in, const int* in_sizes, int n_in,
                              void* d_out, int out_size)
{
    // Robust to metadata ordering: x0 has 6144 elems, params 101,056,512.
    const float* x0     = (const float*)d_in[0];
    const float* params = (const float*)d_in[1];
    if (in_sizes[0] > in_sizes[1]) {
        x0     = (const float*)d_in[1];
        params = (const float*)d_in[0];
    }
    float* outp = (float*)d_out;

    const long OV_SIZE = (long)B_DIM * T_DIM * N_DIM * 3;
    float* ov = outp;                 // output_view (B,T,N,3)
    float* ep = outp + OV_SIZE;       // epiparams   (B,T,N,514)

    init_kernel<<<8, 256>>>(x0);
    ssir_ws_kernel<<<GRID_CTAS, BLOCK_THREADS>>>(x0, params, ov, ep);
}